// round 10
// baseline (speedup 1.0000x reference)
#include <cuda_runtime.h>
#include <cuda_bf16.h>
#include <math.h>

// Problem constants
#define B     8
#define HH    128
#define WW    128
#define NP    16384        // H*W
#define D     27           // PATCH*PATCH*C
#define DP    28           // padded to float4 multiple
#define NA    128          // number of anchors
#define KP    96           // padded split-K (bf16): [hi 28 | lo 28 | hi 28 | 0 x12]
#define KPAIR 48           // KP/2 packed bf16 pairs (uint)
#define PCH   1024         // pixels per chunk (main kernel)
#define NCH   (NP / PCH)   // 16 chunks
#define TPB   512

#define ROWW      52                  // smem pixel-row width in words (48 + 4 pad)
#define SMEM_BYTES (PCH * ROWW * 4)   // 212992 B

// Scratch (device globals)
__device__ __align__(16) float        g_pn  [B * NP * DP];      // [b][p][d] fp32 (window/cross)
__device__ __align__(16) unsigned int g_pbf [B * NP * KPAIR];   // [b][p][48] bf16 pairs (main)
__device__ __align__(16) float        g_sumPart[B * NA * NCH * 4];
__device__ float g_pos  [B * NA];
__device__ float g_in121[B * NA];
__device__ float g_cross[B * NA];
__device__ int   g_cnt  [NA * 3];

// bf16 pair pack: low half = first element
__device__ __forceinline__ unsigned int pack_bf2(__nv_bfloat16 a, __nv_bfloat16 b) {
    return ((unsigned int)__bfloat16_as_ushort(b) << 16) | __bfloat16_as_ushort(a);
}

// mma.sync m16n8k16 bf16: D(f32x4) += A(4xb32) * B(2xb32)
#define MMA_BF16(d, a0, a1, a2, a3, b0, b1)                                    \
    asm volatile(                                                              \
        "mma.sync.aligned.m16n8k16.row.col.f32.bf16.bf16.f32 "                 \
        "{%0,%1,%2,%3}, {%4,%5,%6,%7}, {%8,%9}, {%0,%1,%2,%3};"                \
        : "+f"(d[0]), "+f"(d[1]), "+f"(d[2]), "+f"(d[3])                       \
        : "r"(a0), "r"(a1), "r"(a2), "r"(a3), "r"(b0), "r"(b1))

// ---------------------------------------------------------------------------
// Kernel 1: normalized 3x3 edge-padded patches -> g_pn (fp32) + g_pbf (bf16 split)
// ---------------------------------------------------------------------------
__global__ void patch_kernel(const float* __restrict__ lat)
{
    int idx = blockIdx.x * blockDim.x + threadIdx.x;
    if (idx >= B * NP) return;
    int b = idx >> 14;
    int p = idx & (NP - 1);
    int y = p >> 7;
    int x = p & 127;

    float v[DP];
    float ss = 0.0f;
    int d = 0;
#pragma unroll
    for (int dy = -1; dy <= 1; dy++) {
        int yy = min(max(y + dy, 0), HH - 1);
#pragma unroll
        for (int dx = -1; dx <= 1; dx++) {
            int xx = min(max(x + dx, 0), WW - 1);
            const float* src = lat + (((size_t)(b * HH + yy) * WW + xx) * 3);
            float a0 = src[0], a1 = src[1], a2 = src[2];
            v[d] = a0; v[d + 1] = a1; v[d + 2] = a2;
            ss += a0 * a0 + a1 * a1 + a2 * a2;
            d += 3;
        }
    }
    float inv = 1.0f / fmaxf(sqrtf(ss), 1e-12f);
#pragma unroll
    for (int k = 0; k < D; k++) v[k] *= inv;
    v[D] = 0.0f;

    // fp32 p-major copy (7 x float4)
    float4* dstP = reinterpret_cast<float4*>(g_pn + ((size_t)b * NP + p) * DP);
#pragma unroll
    for (int k = 0; k < DP / 4; k++)
        dstP[k] = make_float4(v[4 * k], v[4 * k + 1], v[4 * k + 2], v[4 * k + 3]);

    // bf16 hi/lo split row: [hi(14 pairs) | lo(14) | hi(14) | 0(6)]
    unsigned int row[KPAIR];
#pragma unroll
    for (int j = 0; j < 14; j++) {
        float a = v[2 * j], c = v[2 * j + 1];
        __nv_bfloat16 ha = __float2bfloat16(a);
        __nv_bfloat16 hc = __float2bfloat16(c);
        __nv_bfloat16 la = __float2bfloat16(a - __bfloat162float(ha));
        __nv_bfloat16 lc = __float2bfloat16(c - __bfloat162float(hc));
        row[j]      = pack_bf2(ha, hc);
        row[14 + j] = pack_bf2(la, lc);
        row[28 + j] = row[j];
    }
#pragma unroll
    for (int j = 42; j < KPAIR; j++) row[j] = 0u;

    uint4* dstB = reinterpret_cast<uint4*>(g_pbf + ((size_t)b * NP + p) * KPAIR);
#pragma unroll
    for (int j = 0; j < KPAIR / 4; j++)
        dstB[j] = make_uint4(row[4 * j], row[4 * j + 1], row[4 * j + 2], row[4 * j + 3]);
}

// ---------------------------------------------------------------------------
// Kernel 2: total exp-sums via bf16 3-split mma.sync.
// grid (NCH, B), block 512 = 16 warps. Warp w: pixel quarter (w&3, 256 pixels
// = 16 m16-tiles), anchor quad (w>>2, 4 n8-tiles = 32 anchors).
// ---------------------------------------------------------------------------
__global__ void __launch_bounds__(TPB)
main_kernel(const int* __restrict__ aidx)
{
    extern __shared__ unsigned int smem[];

    int pc  = blockIdx.x;
    int b   = blockIdx.y;
    int tid = threadIdx.x;
    int w    = tid >> 5;
    int lane = tid & 31;
    int g = lane >> 2;      // groupID
    int t = lane & 3;       // threadID_in_group
    int ag = w >> 2;        // anchor quad 0..3
    int h  = w & 3;         // pixel quarter 0..3

    // Phase 1: stage anchor rows [128][48] with section remap [hi|hi|lo]
    // (pixel rows are [hi|lo|hi]; src pair = (j<14 ? j : j-14) for j<42)
    for (int i = tid; i < NA * KPAIR; i += TPB) {
        int a = i / KPAIR, jj = i % KPAIR;
        unsigned int val = 0u;
        if (jj < 42) {
            int sj = (jj < 14) ? jj : jj - 14;
            val = g_pbf[((size_t)b * NP + aidx[a]) * KPAIR + sj];
        }
        smem[i] = val;
    }
    __syncthreads();

    // Build B fragments (anchors), register-resident: Bf[tile][kstep][2]
    unsigned int Bf[4][6][2];
#pragma unroll
    for (int tt = 0; tt < 4; tt++) {
        int n = (ag * 4 + tt) * 8 + g;
#pragma unroll
        for (int ks = 0; ks < 6; ks++) {
            Bf[tt][ks][0] = smem[n * KPAIR + ks * 8 + t];
            Bf[tt][ks][1] = smem[n * KPAIR + ks * 8 + t + 4];
        }
    }
    __syncthreads();

    // Phase 2: stage pixel chunk [1024 rows][52 words] (rows padded 48->52)
    {
        const uint4* src = reinterpret_cast<const uint4*>(g_pbf)
                         + ((size_t)b * NP + (size_t)pc * PCH) * (KPAIR / 4);
        uint4* dst = reinterpret_cast<uint4*>(smem);
        for (int i = tid; i < PCH * (KPAIR / 4); i += TPB) {
            int p = i / (KPAIR / 4), j = i % (KPAIR / 4);
            dst[p * (ROWW / 4) + j] = src[i];
        }
    }
    __syncthreads();

    float acc[4][2];
#pragma unroll
    for (int tt = 0; tt < 4; tt++) { acc[tt][0] = 0.0f; acc[tt][1] = 0.0f; }

    for (int m = 0; m < 16; m++) {
        int pr = h * 256 + m * 16;
        float Dg[4][4];
#pragma unroll
        for (int tt = 0; tt < 4; tt++)
#pragma unroll
            for (int i = 0; i < 4; i++) Dg[tt][i] = 0.0f;

#pragma unroll
        for (int ks = 0; ks < 6; ks++) {
            unsigned int a0 = smem[(pr + g)     * ROWW + ks * 8 + t];
            unsigned int a1 = smem[(pr + g + 8) * ROWW + ks * 8 + t];
            unsigned int a2 = smem[(pr + g)     * ROWW + ks * 8 + t + 4];
            unsigned int a3 = smem[(pr + g + 8) * ROWW + ks * 8 + t + 4];
#pragma unroll
            for (int tt = 0; tt < 4; tt++)
                MMA_BF16(Dg[tt], a0, a1, a2, a3, Bf[tt][ks][0], Bf[tt][ks][1]);
        }
#pragma unroll
        for (int tt = 0; tt < 4; tt++) {
            acc[tt][0] += __expf(Dg[tt][0]) + __expf(Dg[tt][2]);
            acc[tt][1] += __expf(Dg[tt][1]) + __expf(Dg[tt][3]);
        }
    }

    // Reduce over the 8 groupID lanes (same t): xor 4, 8, 16
#pragma unroll
    for (int tt = 0; tt < 4; tt++) {
#pragma unroll
        for (int c = 0; c < 2; c++) {
            acc[tt][c] += __shfl_xor_sync(0xffffffffu, acc[tt][c], 4);
            acc[tt][c] += __shfl_xor_sync(0xffffffffu, acc[tt][c], 8);
            acc[tt][c] += __shfl_xor_sync(0xffffffffu, acc[tt][c], 16);
        }
    }

    if (g == 0) {   // lanes 0..3 hold anchor columns (2t, 2t+1) per tile
#pragma unroll
        for (int tt = 0; tt < 4; tt++) {
            int n0 = (ag * 4 + tt) * 8 + 2 * t;
            g_sumPart[(((size_t)b * NA + n0    ) * NCH + pc) * 4 + h] = acc[tt][0];
            g_sumPart[(((size_t)b * NA + n0 + 1) * NCH + pc) * 4 + h] = acc[tt][1];
        }
    }
}

// ---------------------------------------------------------------------------
// Kernel 3: window terms (pos, in121, counts) + cross-batch term.
// grid (NA, B), block 128. Contiguous fp32 p-major reads.
// ---------------------------------------------------------------------------
__device__ __forceinline__ float dot_pn(const float4* __restrict__ av,
                                        const float* __restrict__ pk)
{
    const float4* q = reinterpret_cast<const float4*>(pk);
    float dot = 0.0f;
#pragma unroll
    for (int k = 0; k < DP / 4; k++) {
        float4 a = av[k], p = q[k];
        dot = fmaf(a.x, p.x, fmaf(a.y, p.y, fmaf(a.z, p.z, fmaf(a.w, p.w, dot))));
    }
    return dot;
}

__global__ void window_kernel(const int* __restrict__ aidx)
{
    int n = blockIdx.x;
    int b = blockIdx.y;
    int tid = threadIdx.x;

    int ai = aidx[n];
    float4 av[DP / 4];
    {
        const float4* src = reinterpret_cast<const float4*>(
            g_pn + ((size_t)b * NP + ai) * DP);
#pragma unroll
        for (int k = 0; k < DP / 4; k++) av[k] = src[k];
    }

    int ay = ai >> 7, ax = ai & 127;

    float pos = 0.0f, in121 = 0.0f, cross = 0.0f;
    int pcnt = 0, ccnt = 0, c121 = 0;

    // within-batch 23x23 window (d2 <= 121)
    for (int t = tid; t < 23 * 23; t += 128) {
        int dy = t / 23 - 11;
        int dx = t % 23 - 11;
        int d2 = dy * dy + dx * dx;
        int y = ay + dy, x = ax + dx;
        if (d2 <= 121 && y >= 0 && y < HH && x >= 0 && x < WW) {
            c121++;
            if (d2 > 0 && d2 <= 9) pcnt++;
            if (d2 <= 4) ccnt++;
            int p = (y << 7) | x;
            float dot = dot_pn(av, g_pn + ((size_t)b * NP + p) * DP);
            float e = __expf(dot);
            in121 += e;
            if (d2 > 0 && d2 <= 9) pos += e;
        }
    }

    // cross-batch: 13 offsets with d2 <= 4, other batches, T=0.5
    {
        const int ody[13] = {-2,-1,-1,-1, 0, 0, 0, 0, 0, 1, 1, 1, 2};
        const int odx[13] = { 0,-1, 0, 1,-2,-1, 0, 1, 2,-1, 0, 1, 0};
        if (tid < 13 * B) {
            int o = tid >> 3;
            int k = tid & 7;
            int y = ay + ody[o], x = ax + odx[o];
            if (k != b && y >= 0 && y < HH && x >= 0 && x < WW) {
                int p = (y << 7) | x;
                float dot = dot_pn(av, g_pn + ((size_t)k * NP + p) * DP);
                cross += __expf(2.0f * dot);
            }
        }
    }

    // block reduce (4 warps)
    __shared__ float rf[3][4];
    __shared__ int   ri[3][4];
#pragma unroll
    for (int off = 16; off > 0; off >>= 1) {
        pos   += __shfl_xor_sync(0xffffffffu, pos, off);
        in121 += __shfl_xor_sync(0xffffffffu, in121, off);
        cross += __shfl_xor_sync(0xffffffffu, cross, off);
        pcnt  += __shfl_xor_sync(0xffffffffu, pcnt, off);
        ccnt  += __shfl_xor_sync(0xffffffffu, ccnt, off);
        c121  += __shfl_xor_sync(0xffffffffu, c121, off);
    }
    int wid = tid >> 5, lane = tid & 31;
    if (lane == 0) {
        rf[0][wid] = pos; rf[1][wid] = in121; rf[2][wid] = cross;
        ri[0][wid] = pcnt; ri[1][wid] = ccnt; ri[2][wid] = c121;
    }
    __syncthreads();
    if (tid == 0) {
        float P = 0, I = 0, X = 0; int pc2 = 0, cc2 = 0, c12 = 0;
#pragma unroll
        for (int w = 0; w < 4; w++) {
            P += rf[0][w]; I += rf[1][w]; X += rf[2][w];
            pc2 += ri[0][w]; cc2 += ri[1][w]; c12 += ri[2][w];
        }
        g_pos  [(size_t)b * NA + n] = P;
        g_in121[(size_t)b * NA + n] = I;
        g_cross[(size_t)b * NA + n] = X;
        if (b == 0) {
            g_cnt[n * 3 + 0] = pc2;
            g_cnt[n * 3 + 1] = cc2;
            g_cnt[n * 3 + 2] = c12;
        }
    }
}

// ---------------------------------------------------------------------------
// Kernel 4: per-(b,n) loss + global reduce. 1 block, 1024 threads.
// ---------------------------------------------------------------------------
__global__ void __launch_bounds__(1024)
final_kernel(float* __restrict__ out)
{
    int t = threadIdx.x;       // 0..1023
    int b = t >> 7;            // 0..7
    int n = t & 127;           // 0..127

    int pcnt = g_cnt[n * 3 + 0];
    int ccnt = g_cnt[n * 3 + 1];
    int c121 = g_cnt[n * 3 + 2];
    int ncnt = NP - c121;

    const float4* sp = reinterpret_cast<const float4*>(
        g_sumPart + ((size_t)b * NA + n) * (NCH * 4));
    float tsum = 0.0f;
#pragma unroll
    for (int i = 0; i < (NCH * 4) / 4; i++) {
        float4 q = sp[i];
        tsum += q.x + q.y + q.z + q.w;
    }

    float ps = g_pos  [(size_t)b * NA + n];
    float ns = tsum - g_in121[(size_t)b * NA + n];
    float cs = g_cross[(size_t)b * NA + n];

    float pm = (pcnt > 0) ? ps / (float)max(pcnt, 1) : 1.0f;
    float nm = ns / (float)max(ncnt, 1);
    float cm = cs / (float)max((B - 1) * ccnt, 1);
    float lw = -__logf(pm / (pm + nm + 1e-8f));
    float la = -__logf(pm / (pm + cm + 1e-8f));
    float per = (ncnt > 0 ? lw : 0.0f) + (ccnt > 0 ? la : 0.0f);

    bool valid = (pcnt > 0) && (ncnt > 0 || ccnt > 0);
    float tot = valid ? per : 0.0f;
    int   nv  = valid ? 1 : 0;

    __shared__ float sT[1024];
    __shared__ int   sV[1024];
    sT[t] = tot; sV[t] = nv;
    __syncthreads();
    for (int s = 512; s > 0; s >>= 1) {
        if (t < s) { sT[t] += sT[t + s]; sV[t] += sV[t + s]; }
        __syncthreads();
    }
    if (t == 0) out[0] = (sV[0] > 0) ? sT[0] / (float)sV[0] : 0.0f;
}

// ---------------------------------------------------------------------------
extern "C" void kernel_launch(void* const* d_in, const int* in_sizes, int n_in,
                              void* d_out, int out_size)
{
    const float* latents = (const float*)d_in[0];
    const int*   aidx    = (const int*)d_in[1];
    float*       out     = (float*)d_out;

    (void)in_sizes; (void)n_in; (void)out_size;

    cudaFuncSetAttribute(main_kernel,
                         cudaFuncAttributeMaxDynamicSharedMemorySize, SMEM_BYTES);

    patch_kernel<<<(B * NP + 255) / 256, 256>>>(latents);

    dim3 g2(NCH, B);
    main_kernel<<<g2, TPB, SMEM_BYTES>>>(aidx);

    dim3 g3(NA, B);
    window_kernel<<<g3, 128>>>(aidx);

    final_kernel<<<1, 1024>>>(out);
}

// round 13
// speedup vs baseline: 1.2804x; 1.2804x over previous
#include <cuda_runtime.h>
#include <cuda_fp16.h>
#include <math.h>
#include <stdint.h>

// Problem constants
#define B    8
#define HH   128
#define WW   128
#define NP   16384        // H*W
#define D    27           // PATCH*PATCH*C
#define DP   28           // padded
#define NA   128          // number of anchors
#define AG   16           // anchors per group (main kernel)
#define NG   (NA / AG)    // 8 anchor groups
#define PC   16           // p-chunks
#define PCHUNK (NP / PC)  // 1024 pixels per chunk
#define TPB  256
#define LOG2E 1.4426950408889634f

// Scratch (device globals)
__device__ __align__(16) float  g_pn[B * NP * DP];   // [b][p][d] fp32 (window/cross/anchors)
__device__ __align__(16) __half g_ph[B * DP * NP];   // [b][d][p] fp16 d-major (main kernel)
__device__ __align__(16) float  g_sumPart[B * NA * PC];
__device__ float g_pos  [B * NA];
__device__ float g_in121[B * NA];
__device__ float g_cross[B * NA];
__device__ int   g_cnt  [NA * 3];

__device__ __forceinline__ float ex2_approx(float x) {
    float y;
    asm("ex2.approx.f32 %0, %1;" : "=f"(y) : "f"(x));
    return y;
}

// ---------------------------------------------------------------------------
// Kernel 1: normalized 3x3 edge-padded patches -> g_pn (fp32 p-major)
//           + g_ph (fp16 d-major)
// ---------------------------------------------------------------------------
__global__ void patch_kernel(const float* __restrict__ lat)
{
    int idx = blockIdx.x * blockDim.x + threadIdx.x;
    if (idx >= B * NP) return;
    int b = idx >> 14;
    int p = idx & (NP - 1);
    int y = p >> 7;
    int x = p & 127;

    float v[DP];
    float ss = 0.0f;
    int d = 0;
#pragma unroll
    for (int dy = -1; dy <= 1; dy++) {
        int yy = min(max(y + dy, 0), HH - 1);
#pragma unroll
        for (int dx = -1; dx <= 1; dx++) {
            int xx = min(max(x + dx, 0), WW - 1);
            const float* src = lat + (((size_t)(b * HH + yy) * WW + xx) * 3);
            float a0 = src[0], a1 = src[1], a2 = src[2];
            v[d] = a0; v[d + 1] = a1; v[d + 2] = a2;
            ss += a0 * a0 + a1 * a1 + a2 * a2;
            d += 3;
        }
    }
    float inv = 1.0f / fmaxf(sqrtf(ss), 1e-12f);
#pragma unroll
    for (int k = 0; k < D; k++) v[k] *= inv;
    v[D] = 0.0f;

    // fp32 p-major copy (7 x float4)
    float4* dstP = reinterpret_cast<float4*>(g_pn + ((size_t)b * NP + p) * DP);
#pragma unroll
    for (int k = 0; k < DP / 4; k++)
        dstP[k] = make_float4(v[4 * k], v[4 * k + 1], v[4 * k + 2], v[4 * k + 3]);

    // fp16 d-major copy (strided 2B stores, coalesced across p)
    __half* dstH = g_ph + (size_t)b * DP * NP + p;
#pragma unroll
    for (int k = 0; k < DP; k++)
        dstH[(size_t)k * NP] = __float2half(v[k]);
}

// ---------------------------------------------------------------------------
// Kernel 2: UNMASKED total exp-sums via HFMA2 (2 fp16 MACs per issue slot).
// grid (PC, NG, B), block 256. Each thread: 4 pixels x 16 anchors.
// Pixel pairs (p0,p1),(p2,p3) are native half2 from LDG.64; anchors pre-scaled
// by log2(e), quantized to fp16, duplicated into half2 in shared (broadcast LDS).
// dot accumulated in half2; exp via ex2.approx of the converted fp32.
// ---------------------------------------------------------------------------
__global__ void __launch_bounds__(TPB, 2)
main_kernel(const int* __restrict__ aidx)
{
    int pc = blockIdx.x;
    int nt = blockIdx.y;
    int b  = blockIdx.z;
    int tid = threadIdx.x;

    __shared__ unsigned int sA[AG * DP];   // duplicated half2 (a_d, a_d), row = 112B
    __shared__ float rS[AG][TPB / 32];

    for (int t = tid; t < AG * DP; t += TPB) {
        int a = t / DP, dd = t % DP;
        float w = 0.0f;
        if (dd < D)
            w = g_pn[((size_t)b * NP + aidx[nt * AG + a]) * DP + dd] * LOG2E;
        __half2 hh = __half2half2(__float2half(w));
        sA[t] = *reinterpret_cast<unsigned int*>(&hh);
    }
    __syncthreads();

    const __half* pb = g_ph + (size_t)b * DP * NP;
    int p0 = pc * PCHUNK + tid * 4;

    __half2 acc[AG][2];
#pragma unroll
    for (int a = 0; a < AG; a++) {
        acc[a][0] = __half2half2(__float2half(0.0f));
        acc[a][1] = acc[a][0];
    }

#pragma unroll
    for (int dq = 0; dq < DP / 4; dq++) {
        __half2 v[4][2];
#pragma unroll
        for (int j = 0; j < 4; j++) {
            uint2 raw = *reinterpret_cast<const uint2*>(pb + (size_t)(dq * 4 + j) * NP + p0);
            v[j][0] = *reinterpret_cast<__half2*>(&raw.x);
            v[j][1] = *reinterpret_cast<__half2*>(&raw.y);
        }
#pragma unroll
        for (int a = 0; a < AG; a++) {
            uint4 w = *reinterpret_cast<const uint4*>(&sA[a * DP + dq * 4]);
            __half2 w0 = *reinterpret_cast<__half2*>(&w.x);
            __half2 w1 = *reinterpret_cast<__half2*>(&w.y);
            __half2 w2 = *reinterpret_cast<__half2*>(&w.z);
            __half2 w3 = *reinterpret_cast<__half2*>(&w.w);
            acc[a][0] = __hfma2(v[0][0], w0, acc[a][0]);
            acc[a][1] = __hfma2(v[0][1], w0, acc[a][1]);
            acc[a][0] = __hfma2(v[1][0], w1, acc[a][0]);
            acc[a][1] = __hfma2(v[1][1], w1, acc[a][1]);
            acc[a][0] = __hfma2(v[2][0], w2, acc[a][0]);
            acc[a][1] = __hfma2(v[2][1], w2, acc[a][1]);
            acc[a][0] = __hfma2(v[3][0], w3, acc[a][0]);
            acc[a][1] = __hfma2(v[3][1], w3, acc[a][1]);
        }
    }

    float s[AG];
#pragma unroll
    for (int a = 0; a < AG; a++) {
        float2 f0 = __half22float2(acc[a][0]);
        float2 f1 = __half22float2(acc[a][1]);
        s[a] = ex2_approx(f0.x) + ex2_approx(f0.y)
             + ex2_approx(f1.x) + ex2_approx(f1.y);
#pragma unroll
        for (int off = 16; off > 0; off >>= 1)
            s[a] += __shfl_xor_sync(0xffffffffu, s[a], off);
    }

    int wid = tid >> 5, lane = tid & 31;
    if (lane == 0) {
#pragma unroll
        for (int a = 0; a < AG; a++) rS[a][wid] = s[a];
    }
    __syncthreads();

    if (tid < AG) {
        float t = 0.0f;
#pragma unroll
        for (int w = 0; w < TPB / 32; w++) t += rS[tid][w];
        int n = nt * AG + tid;
        g_sumPart[((size_t)b * NA + n) * PC + pc] = t;
    }
}

// ---------------------------------------------------------------------------
// Kernel 3: window terms (pos, in121, counts) + cross-batch term. All fp32.
// grid (NA, B), block 128. Contiguous p-major reads.
// ---------------------------------------------------------------------------
__device__ __forceinline__ float dot_pn(const float4* __restrict__ av,
                                        const float* __restrict__ pk)
{
    const float4* q = reinterpret_cast<const float4*>(pk);
    float dot = 0.0f;
#pragma unroll
    for (int k = 0; k < DP / 4; k++) {
        float4 a = av[k], p = q[k];
        dot = fmaf(a.x, p.x, fmaf(a.y, p.y, fmaf(a.z, p.z, fmaf(a.w, p.w, dot))));
    }
    return dot;
}

__global__ void window_kernel(const int* __restrict__ aidx)
{
    int n = blockIdx.x;
    int b = blockIdx.y;
    int tid = threadIdx.x;

    int ai = aidx[n];
    float4 av[DP / 4];
    {
        const float4* src = reinterpret_cast<const float4*>(
            g_pn + ((size_t)b * NP + ai) * DP);
#pragma unroll
        for (int k = 0; k < DP / 4; k++) av[k] = src[k];
    }

    int ay = ai >> 7, ax = ai & 127;

    float pos = 0.0f, in121 = 0.0f, cross = 0.0f;
    int pcnt = 0, ccnt = 0, c121 = 0;

    // within-batch 23x23 window (d2 <= 121)
    for (int t = tid; t < 23 * 23; t += 128) {
        int dy = t / 23 - 11;
        int dx = t % 23 - 11;
        int d2 = dy * dy + dx * dx;
        int y = ay + dy, x = ax + dx;
        if (d2 <= 121 && y >= 0 && y < HH && x >= 0 && x < WW) {
            c121++;
            if (d2 > 0 && d2 <= 9) pcnt++;
            if (d2 <= 4) ccnt++;
            int p = (y << 7) | x;
            float dot = dot_pn(av, g_pn + ((size_t)b * NP + p) * DP);
            float e = __expf(dot);
            in121 += e;
            if (d2 > 0 && d2 <= 9) pos += e;
        }
    }

    // cross-batch: 13 offsets with d2 <= 4, other batches, T=0.5
    {
        const int ody[13] = {-2,-1,-1,-1, 0, 0, 0, 0, 0, 1, 1, 1, 2};
        const int odx[13] = { 0,-1, 0, 1,-2,-1, 0, 1, 2,-1, 0, 1, 0};
        if (tid < 13 * B) {
            int o = tid >> 3;
            int k = tid & 7;
            int y = ay + ody[o], x = ax + odx[o];
            if (k != b && y >= 0 && y < HH && x >= 0 && x < WW) {
                int p = (y << 7) | x;
                float dot = dot_pn(av, g_pn + ((size_t)k * NP + p) * DP);
                cross += __expf(2.0f * dot);
            }
        }
    }

    // block reduce (4 warps)
    __shared__ float rf[3][4];
    __shared__ int   ri[3][4];
#pragma unroll
    for (int off = 16; off > 0; off >>= 1) {
        pos   += __shfl_xor_sync(0xffffffffu, pos, off);
        in121 += __shfl_xor_sync(0xffffffffu, in121, off);
        cross += __shfl_xor_sync(0xffffffffu, cross, off);
        pcnt  += __shfl_xor_sync(0xffffffffu, pcnt, off);
        ccnt  += __shfl_xor_sync(0xffffffffu, ccnt, off);
        c121  += __shfl_xor_sync(0xffffffffu, c121, off);
    }
    int wid = tid >> 5, lane = tid & 31;
    if (lane == 0) {
        rf[0][wid] = pos; rf[1][wid] = in121; rf[2][wid] = cross;
        ri[0][wid] = pcnt; ri[1][wid] = ccnt; ri[2][wid] = c121;
    }
    __syncthreads();
    if (tid == 0) {
        float P = 0, I = 0, X = 0; int pc2 = 0, cc2 = 0, c12 = 0;
#pragma unroll
        for (int w = 0; w < 4; w++) {
            P += rf[0][w]; I += rf[1][w]; X += rf[2][w];
            pc2 += ri[0][w]; cc2 += ri[1][w]; c12 += ri[2][w];
        }
        g_pos  [(size_t)b * NA + n] = P;
        g_in121[(size_t)b * NA + n] = I;
        g_cross[(size_t)b * NA + n] = X;
        if (b == 0) {
            g_cnt[n * 3 + 0] = pc2;
            g_cnt[n * 3 + 1] = cc2;
            g_cnt[n * 3 + 2] = c12;
        }
    }
}

// ---------------------------------------------------------------------------
// Kernel 4: per-(b,n) loss + global reduce. 1 block, 1024 threads.
// ---------------------------------------------------------------------------
__global__ void __launch_bounds__(1024)
final_kernel(float* __restrict__ out)
{
    int t = threadIdx.x;       // 0..1023
    int b = t >> 7;            // 0..7
    int n = t & 127;           // 0..127

    int pcnt = g_cnt[n * 3 + 0];
    int ccnt = g_cnt[n * 3 + 1];
    int c121 = g_cnt[n * 3 + 2];
    int ncnt = NP - c121;

    const float4* sp = reinterpret_cast<const float4*>(
        g_sumPart + ((size_t)b * NA + n) * PC);
    float tsum = 0.0f;
#pragma unroll
    for (int i = 0; i < PC / 4; i++) {
        float4 q = sp[i];
        tsum += q.x + q.y + q.z + q.w;
    }

    float ps = g_pos  [(size_t)b * NA + n];
    float ns = tsum - g_in121[(size_t)b * NA + n];
    float cs = g_cross[(size_t)b * NA + n];

    float pm = (pcnt > 0) ? ps / (float)max(pcnt, 1) : 1.0f;
    float nm = ns / (float)max(ncnt, 1);
    float cm = cs / (float)max((B - 1) * ccnt, 1);
    float lw = -__logf(pm / (pm + nm + 1e-8f));
    float la = -__logf(pm / (pm + cm + 1e-8f));
    float per = (ncnt > 0 ? lw : 0.0f) + (ccnt > 0 ? la : 0.0f);

    bool valid = (pcnt > 0) && (ncnt > 0 || ccnt > 0);
    float tot = valid ? per : 0.0f;
    int   nv  = valid ? 1 : 0;

    __shared__ float sT[1024];
    __shared__ int   sV[1024];
    sT[t] = tot; sV[t] = nv;
    __syncthreads();
    for (int s = 512; s > 0; s >>= 1) {
        if (t < s) { sT[t] += sT[t + s]; sV[t] += sV[t + s]; }
        __syncthreads();
    }
    if (t == 0) out[0] = (sV[0] > 0) ? sT[0] / (float)sV[0] : 0.0f;
}

// ---------------------------------------------------------------------------
extern "C" void kernel_launch(void* const* d_in, const int* in_sizes, int n_in,
                              void* d_out, int out_size)
{
    const float* latents = (const float*)d_in[0];
    const int*   aidx    = (const int*)d_in[1];
    float*       out     = (float*)d_out;

    (void)in_sizes; (void)n_in; (void)out_size;

    patch_kernel<<<(B * NP + 255) / 256, 256>>>(latents);

    dim3 g2(PC, NG, B);
    main_kernel<<<g2, TPB>>>(aidx);

    dim3 g3(NA, B);
    window_kernel<<<g3, 128>>>(aidx);

    final_kernel<<<1, 1024>>>(out);
}